// round 2
// baseline (speedup 1.0000x reference)
#include <cuda_runtime.h>
#include <cstdint>

#define D        128
#define DH       32
#define P_SEG    16384
#define SEG_PER_BLOCK 16
#define NBLOCKS  (P_SEG / SEG_PER_BLOCK)
#define TILE     256
#define THREADS  256
#define XP_STRIDE 257                   // 8-byte units per kp-row (odd -> conflict-free transpose)
#define SMEM_ULL (64 * DH + 16 * XP_STRIDE)   // W pairs + x tile, in 8B units
#define NROWS_MAX 1000000

__device__ int   g_seg_start[P_SEG + 1];
__device__ float g_e[NROWS_MAX];

__device__ __forceinline__ unsigned long long pack2(float lo, float hi) {
    unsigned long long r;
    asm("mov.b64 %0, {%1, %2};" : "=l"(r) : "f"(lo), "f"(hi));
    return r;
}
__device__ __forceinline__ void unpack2(unsigned long long v, float& lo, float& hi) {
    asm("mov.b64 {%0, %1}, %2;" : "=f"(lo), "=f"(hi) : "l"(v));
}
// Packed dual-fp32 FMA (FFMA2) — 2x fp32 MAC throughput on sm_103a
__device__ __forceinline__ unsigned long long fma2(unsigned long long a,
                                                   unsigned long long b,
                                                   unsigned long long c) {
    unsigned long long d;
    asm("fma.rn.f32x2 %0, %1, %2, %3;" : "=l"(d) : "l"(a), "l"(b), "l"(c));
    return d;
}

// Kernel 1: segment boundaries via binary search over sorted person_ids.
__global__ void seg_bounds_kernel(const int* __restrict__ pids, int n) {
    int p = blockIdx.x * blockDim.x + threadIdx.x;
    if (p > P_SEG) return;
    int lo = 0, hi = n;
    while (lo < hi) {
        int mid = (lo + hi) >> 1;
        if (pids[mid] < p) lo = mid + 1; else hi = mid;
    }
    g_seg_start[p] = lo;
}

// Kernel 2: fused scores + segment softmax + weighted pooling.
// One block owns 16 contiguous segments (contiguous row range).
__global__ __launch_bounds__(THREADS, 1)
void pool_kernel(const float* __restrict__ x, const int* __restrict__ pids,
                 const float* __restrict__ W1, const float* __restrict__ b1,
                 const float* __restrict__ W2, const float* __restrict__ b2,
                 float* __restrict__ out, int has_pids) {
    extern __shared__ unsigned long long dynsm[];
    unsigned long long* sWp = dynsm;             // [64][32] f32x2 pairs {W1[2k][h], W1[2k+1][h]}
    unsigned long long* sXp = dynsm + 64 * DH;   // [16][XP_STRIDE] transposed x pairs
    __shared__ float sW2[DH];
    __shared__ float sB1[DH];
    __shared__ int   sStart[SEG_PER_BLOCK + 1];
    __shared__ float sDen[SEG_PER_BLOCK];

    const int tid    = threadIdx.x;
    const int warpId = tid >> 5;
    const int lane   = tid & 31;
    const int seg0   = blockIdx.x * SEG_PER_BLOCK;

    if (tid <= SEG_PER_BLOCK) sStart[tid] = g_seg_start[seg0 + tid];
    if (tid < DH) { sW2[tid] = W2[tid]; sB1[tid] = b1[tid]; }
    if (tid < SEG_PER_BLOCK) sDen[tid] = 0.f;
    for (int i = tid; i < 64 * DH; i += THREADS) {
        int kp = i >> 5, h = i & 31;
        sWp[i] = pack2(W1[(2 * kp) * DH + h], W1[(2 * kp + 1) * DH + h]);
    }
    const float b2v = b2[0];
    __syncthreads();

    const int rbeg = sStart[0], rend = sStart[SEG_PER_BLOCK];

    // ---- Phase A: per-row attention score -> e = exp(score), shared denom ----
    for (int tbase = rbeg; tbase < rend; tbase += TILE) {
        const int row = tbase + tid;
        const bool act = row < rend;
        unsigned long long acc[DH];
        #pragma unroll
        for (int h = 0; h < DH; ++h) acc[h] = pack2(sB1[h], 0.f);

        for (int chunk = 0; chunk < 4; ++chunk) {
            __syncthreads();
            // stage 256 rows x 32 k, transposed into k-pair-major layout
            for (int rr = warpId; rr < TILE; rr += 8) {
                int r2 = tbase + rr;
                float v = 0.f;
                if (r2 < rend) v = x[r2 * D + chunk * 32 + lane];
                ((float*)(sXp + (lane >> 1) * XP_STRIDE + rr))[lane & 1] = v;
            }
            __syncthreads();
            if (act) {
                #pragma unroll 4
                for (int kp = 0; kp < 16; ++kp) {
                    unsigned long long xp = sXp[kp * XP_STRIDE + tid];
                    const unsigned long long* wrow = sWp + (chunk * 16 + kp) * DH;
                    #pragma unroll
                    for (int h = 0; h < DH; ++h)
                        acc[h] = fma2(xp, wrow[h], acc[h]);
                }
            }
        }
        if (act) {
            float score = b2v;
            #pragma unroll
            for (int h = 0; h < DH; ++h) {
                float lo, hi; unpack2(acc[h], lo, hi);
                score += tanhf(lo + hi) * sW2[h];
            }
            // |score| <= ~6 analytically: exp without max-subtraction is safe
            float e = __expf(score);
            g_e[row] = e;
            int sg = pids[row] - seg0;
            atomicAdd(&sDen[sg], e);
        }
    }
    __syncthreads();

    // ---- Phase B: weighted pooling; warp w handles segments w, w+8 ----
    for (int s = warpId; s < SEG_PER_BLOCK; s += 8) {
        const int a = sStart[s], bnd = sStart[s + 1];
        const float den  = sDen[s];
        const float dinv = den > 0.f ? 1.f / den : 0.f;
        float4 acc4 = make_float4(0.f, 0.f, 0.f, 0.f);
        #pragma unroll 4
        for (int r = a; r < bnd; ++r) {
            float w = g_e[r] * dinv;
            float4 xv = *(const float4*)(x + r * D + lane * 4);
            acc4.x = fmaf(w, xv.x, acc4.x);
            acc4.y = fmaf(w, xv.y, acc4.y);
            acc4.z = fmaf(w, xv.z, acc4.z);
            acc4.w = fmaf(w, xv.w, acc4.w);
        }
        *(float4*)(out + (seg0 + s) * D + lane * 4) = acc4;
    }

    // ---- pooled_pids tail (arange), if the output buffer includes it ----
    if (has_pids && tid < SEG_PER_BLOCK) {
        out[P_SEG * D + seg0 + tid] = (float)(seg0 + tid);
    }
}

extern "C" void kernel_launch(void* const* d_in, const int* in_sizes, int n_in,
                              void* d_out, int out_size) {
    const float* x   = (const float*)d_in[0];
    const int*   pid = (const int*)d_in[1];
    const float* W1  = (const float*)d_in[2];
    const float* b1  = (const float*)d_in[3];
    const float* W2  = (const float*)d_in[4];
    const float* b2  = (const float*)d_in[5];
    const int n = in_sizes[1];
    const int has_pids = (out_size >= P_SEG * D + P_SEG) ? 1 : 0;

    seg_bounds_kernel<<<(P_SEG + 1 + 255) / 256, 256>>>(pid, n);

    cudaFuncSetAttribute((const void*)pool_kernel,
                         cudaFuncAttributeMaxDynamicSharedMemorySize,
                         SMEM_ULL * 8);
    pool_kernel<<<NBLOCKS, THREADS, SMEM_ULL * 8>>>(
        x, pid, W1, b1, W2, b2, (float*)d_out, has_pids);
}

// round 3
// speedup vs baseline: 2.4300x; 2.4300x over previous
#include <cuda_runtime.h>
#include <cstdint>

#define D        128
#define DH       32
#define P_SEG    16384
#define SEG_PER_BLOCK 16
#define NBLOCKS  (P_SEG / SEG_PER_BLOCK)
#define THREADS  256
#define TILE_M   256
#define KC       32
#define NCHUNK   (D / KC)          // 4
#define XSTRIDE  258               // floats per staged k-row (even => 8B-aligned pairs)
#define NROWS_MAX 1000000

__device__ int   g_seg_start[P_SEG + 1];
__device__ float g_e[NROWS_MAX];

typedef unsigned long long ull;

__device__ __forceinline__ ull pack2(float lo, float hi) {
    ull r;
    asm("mov.b64 %0, {%1, %2};" : "=l"(r) : "f"(lo), "f"(hi));
    return r;
}
__device__ __forceinline__ void unpack2(ull v, float& lo, float& hi) {
    asm("mov.b64 {%0, %1}, %2;" : "=f"(lo), "=f"(hi) : "l"(v));
}
// Packed dual-fp32 FMA (FFMA2) — 2x fp32 MAC throughput on sm_103a
__device__ __forceinline__ ull fma2(ull a, ull b, ull c) {
    ull d;
    asm("fma.rn.f32x2 %0, %1, %2, %3;" : "=l"(d) : "l"(a), "l"(b), "l"(c));
    return d;
}

// Kernel 1: segment boundaries via binary search over sorted person_ids.
__global__ void seg_bounds_kernel(const int* __restrict__ pids, int n) {
    int p = blockIdx.x * blockDim.x + threadIdx.x;
    if (p > P_SEG) return;
    int lo = 0, hi = n;
    while (lo < hi) {
        int mid = (lo + hi) >> 1;
        if (pids[mid] < p) lo = mid + 1; else hi = mid;
    }
    g_seg_start[p] = lo;
}

__device__ __forceinline__ void ldg_chunk(const float* __restrict__ x,
                                          int tbase, int k0, int rend, int tid,
                                          float4* buf) {
    #pragma unroll
    for (int i = 0; i < 8; ++i) {
        int idx = tid + THREADS * i;
        int row = idx >> 3;          // 0..255
        int kq  = idx & 7;           // 0..7 (float4 within the 32-k chunk)
        int r   = tbase + row;
        if (r < rend)
            buf[i] = *(const float4*)(x + r * D + k0 + kq * 4);
        else
            buf[i] = make_float4(0.f, 0.f, 0.f, 0.f);
    }
}

// Kernel 2: fused scores + segment softmax + weighted pooling.
// One block owns 16 contiguous segments (a contiguous row range).
__global__ __launch_bounds__(THREADS, 2)
void pool_kernel(const float* __restrict__ x, const int* __restrict__ pids,
                 const float* __restrict__ W1, const float* __restrict__ b1,
                 const float* __restrict__ W2, const float* __restrict__ b2,
                 float* __restrict__ out, int has_pids) {
    extern __shared__ float dynsm[];
    float* sXT   = dynsm;                                  // [KC][XSTRIDE] transposed x chunk
    ull*   sWd   = (ull*)(dynsm + KC * XSTRIDE);           // [128][32] dup pairs {w,w}
    float* sScore = (float*)(sWd + D * DH);                // [TILE_M]
    __shared__ float sW2[DH];
    __shared__ float sB1[DH];
    __shared__ int   sStart[SEG_PER_BLOCK + 1];
    __shared__ float sDen[SEG_PER_BLOCK];

    const int tid  = threadIdx.x;
    const int tx   = tid & 31;     // lane; indexes row-pairs
    const int ty   = tid >> 5;     // warp id; indexes hidden group (ty*4..ty*4+3)
    const int seg0 = blockIdx.x * SEG_PER_BLOCK;

    if (tid <= SEG_PER_BLOCK) sStart[tid] = g_seg_start[seg0 + tid];
    if (tid < DH) { sW2[tid] = W2[tid]; sB1[tid] = b1[tid]; }
    if (tid < SEG_PER_BLOCK) sDen[tid] = 0.f;
    for (int i = tid; i < D * DH; i += THREADS) {
        float w = W1[i];
        sWd[i] = pack2(w, w);
    }
    sScore[tid] = 0.f;
    const float b2v = b2[0];
    __syncthreads();

    const int rbeg = sStart[0], rend = sStart[SEG_PER_BLOCK];
    const int nTiles = (rend - rbeg + TILE_M - 1) / TILE_M;

    float4 buf[8];
    if (nTiles > 0) ldg_chunk(x, rbeg, 0, rend, tid, buf);

    // ---- Phase A: register-blocked score GEMM + exp + shared denom ----
    for (int t = 0; t < nTiles; ++t) {
        const int tbase = rbeg + t * TILE_M;
        ull acc[4][4];
        #pragma unroll
        for (int j = 0; j < 4; ++j)
            #pragma unroll
            for (int jh = 0; jh < 4; ++jh) acc[j][jh] = 0ULL;

        for (int c = 0; c < NCHUNK; ++c) {
            __syncthreads();   // previous compute done reading sXT
            // stage chunk c from prefetch regs (transposed)
            #pragma unroll
            for (int i = 0; i < 8; ++i) {
                int idx = tid + THREADS * i;
                int row = idx >> 3;
                int kq  = idx & 7;
                float* dst = sXT + (kq * 4) * XSTRIDE + row;
                dst[0 * XSTRIDE] = buf[i].x;
                dst[1 * XSTRIDE] = buf[i].y;
                dst[2 * XSTRIDE] = buf[i].z;
                dst[3 * XSTRIDE] = buf[i].w;
            }
            __syncthreads();
            // prefetch next chunk (next k-chunk, or next tile's chunk 0)
            int nc = c + 1, nb = tbase;
            if (nc == NCHUNK) { nc = 0; nb += TILE_M; }
            if (nb < rend) ldg_chunk(x, nb, nc * KC, rend, tid, buf);

            // compute: 32 k-steps x 16 fma2
            const int k0 = c * KC;
            #pragma unroll 8
            for (int kk = 0; kk < KC; ++kk) {
                const ull* xrow = (const ull*)(sXT + kk * XSTRIDE);
                ull xp0 = xrow[tx];
                ull xp1 = xrow[tx + 32];
                ull xp2 = xrow[tx + 64];
                ull xp3 = xrow[tx + 96];
                const ull* wrow = sWd + (k0 + kk) * DH + ty * 4;
                ull w0 = wrow[0], w1 = wrow[1], w2 = wrow[2], w3 = wrow[3];
                acc[0][0] = fma2(xp0, w0, acc[0][0]);
                acc[0][1] = fma2(xp0, w1, acc[0][1]);
                acc[0][2] = fma2(xp0, w2, acc[0][2]);
                acc[0][3] = fma2(xp0, w3, acc[0][3]);
                acc[1][0] = fma2(xp1, w0, acc[1][0]);
                acc[1][1] = fma2(xp1, w1, acc[1][1]);
                acc[1][2] = fma2(xp1, w2, acc[1][2]);
                acc[1][3] = fma2(xp1, w3, acc[1][3]);
                acc[2][0] = fma2(xp2, w0, acc[2][0]);
                acc[2][1] = fma2(xp2, w1, acc[2][1]);
                acc[2][2] = fma2(xp2, w2, acc[2][2]);
                acc[2][3] = fma2(xp2, w3, acc[2][3]);
                acc[3][0] = fma2(xp3, w0, acc[3][0]);
                acc[3][1] = fma2(xp3, w1, acc[3][1]);
                acc[3][2] = fma2(xp3, w2, acc[3][2]);
                acc[3][3] = fma2(xp3, w3, acc[3][3]);
            }
        }

        // partial scores: tanh + W2 over this thread's 4 hidden, per row-pair
        #pragma unroll
        for (int j = 0; j < 4; ++j) {
            float slo = 0.f, shi = 0.f;
            #pragma unroll
            for (int jh = 0; jh < 4; ++jh) {
                int h = ty * 4 + jh;
                float lo, hi;
                unpack2(acc[j][jh], lo, hi);
                slo += tanhf(lo + sB1[h]) * sW2[h];
                shi += tanhf(hi + sB1[h]) * sW2[h];
            }
            int p = tx + 32 * j;
            atomicAdd(&sScore[2 * p],     slo);
            atomicAdd(&sScore[2 * p + 1], shi);
        }
        __syncthreads();

        // finalize: one thread per row. |score| <= ~6 analytically, exp safe.
        int row = tbase + tid;
        if (row < rend) {
            float e = __expf(sScore[tid] + b2v);
            g_e[row] = e;
            atomicAdd(&sDen[pids[row] - seg0], e);
        }
        sScore[tid] = 0.f;   // own slot only; next tile's atomics are sync-ordered after this
    }
    __syncthreads();

    // ---- Phase B: weighted pooling; warp ty handles segments ty, ty+8 ----
    for (int s = ty; s < SEG_PER_BLOCK; s += 8) {
        const int a = sStart[s], bnd = sStart[s + 1];
        const float den  = sDen[s];
        const float dinv = den > 0.f ? 1.f / den : 0.f;
        float4 acc4 = make_float4(0.f, 0.f, 0.f, 0.f);
        #pragma unroll 8
        for (int r = a; r < bnd; ++r) {
            float w = g_e[r] * dinv;
            float4 xv = *(const float4*)(x + r * D + tx * 4);
            acc4.x = fmaf(w, xv.x, acc4.x);
            acc4.y = fmaf(w, xv.y, acc4.y);
            acc4.z = fmaf(w, xv.z, acc4.z);
            acc4.w = fmaf(w, xv.w, acc4.w);
        }
        *(float4*)(out + (seg0 + s) * D + tx * 4) = acc4;
    }

    // ---- pooled_pids tail (arange), if the output buffer includes it ----
    if (has_pids && tid < SEG_PER_BLOCK) {
        out[P_SEG * D + seg0 + tid] = (float)(seg0 + tid);
    }
}

extern "C" void kernel_launch(void* const* d_in, const int* in_sizes, int n_in,
                              void* d_out, int out_size) {
    const float* x   = (const float*)d_in[0];
    const int*   pid = (const int*)d_in[1];
    const float* W1  = (const float*)d_in[2];
    const float* b1  = (const float*)d_in[3];
    const float* W2  = (const float*)d_in[4];
    const float* b2  = (const float*)d_in[5];
    const int n = in_sizes[1];
    const int has_pids = (out_size >= P_SEG * D + P_SEG) ? 1 : 0;

    seg_bounds_kernel<<<(P_SEG + 1 + 255) / 256, 256>>>(pid, n);

    const int smem_bytes = (KC * XSTRIDE) * 4 + (D * DH) * 8 + TILE_M * 4;
    cudaFuncSetAttribute((const void*)pool_kernel,
                         cudaFuncAttributeMaxDynamicSharedMemorySize,
                         smem_bytes);
    pool_kernel<<<NBLOCKS, THREADS, smem_bytes>>>(
        x, pid, W1, b1, W2, b2, (float*)d_out, has_pids);
}

// round 5
// speedup vs baseline: 2.5805x; 1.0620x over previous
#include <cuda_runtime.h>
#include <cstdint>

#define D        128
#define DH       32
#define P_SEG    16384
#define SEG_PER_BLOCK 16
#define NBLOCKS  (P_SEG / SEG_PER_BLOCK)
#define THREADS  256
#define TILE_M   256
#define KC       32
#define NCHUNK   (D / KC)          // 4
#define XSTRIDE  258               // floats per staged k-row (even => 8B-aligned pairs)
#define NROWS_MAX 1000000

__device__ int   g_seg_start[P_SEG + 1];
__device__ float g_e[NROWS_MAX];

typedef unsigned long long ull;

__device__ __forceinline__ ull pack2(float lo, float hi) {
    ull r;
    asm("mov.b64 %0, {%1, %2};" : "=l"(r) : "f"(lo), "f"(hi));
    return r;
}
__device__ __forceinline__ void unpack2(ull v, float& lo, float& hi) {
    asm("mov.b64 {%0, %1}, %2;" : "=f"(lo), "=f"(hi) : "l"(v));
}
// Packed dual-fp32 FMA (FFMA2) — 2x fp32 MAC throughput on sm_103a
__device__ __forceinline__ ull fma2(ull a, ull b, ull c) {
    ull d;
    asm("fma.rn.f32x2 %0, %1, %2, %3;" : "=l"(d) : "l"(a), "l"(b), "l"(c));
    return d;
}
// Single-instruction tanh (MUFU-class). Max err ~1e-5 abs -> pooled err ~1e-4 << 1e-3.
__device__ __forceinline__ float tanh_fast(float x) {
    float y;
    asm("tanh.approx.f32 %0, %1;" : "=f"(y) : "f"(x));
    return y;
}

// Kernel 1: segment boundaries via binary search over sorted person_ids.
__global__ void seg_bounds_kernel(const int* __restrict__ pids, int n) {
    int p = blockIdx.x * blockDim.x + threadIdx.x;
    if (p > P_SEG) return;
    int lo = 0, hi = n;
    while (lo < hi) {
        int mid = (lo + hi) >> 1;
        if (pids[mid] < p) lo = mid + 1; else hi = mid;
    }
    g_seg_start[p] = lo;
}

__device__ __forceinline__ void ldg_chunk(const float* __restrict__ x,
                                          int tbase, int k0, int rend, int tid,
                                          float4* buf) {
    #pragma unroll
    for (int i = 0; i < 8; ++i) {
        int idx = tid + THREADS * i;
        int row = idx >> 3;          // 0..255
        int kq  = idx & 7;           // 0..7 (float4 within the 32-k chunk)
        int r   = tbase + row;
        if (r < rend)
            buf[i] = *(const float4*)(x + r * D + k0 + kq * 4);
        else
            buf[i] = make_float4(0.f, 0.f, 0.f, 0.f);
    }
}

// Kernel 2: fused scores + segment softmax + weighted pooling.
// One block owns 16 contiguous segments (a contiguous row range).
// Thread tile: 2 row-pairs x 8 hidden (16 FFMA2/k-step) -> LDS/FMA co-bound.
__global__ __launch_bounds__(THREADS, 2)
void pool_kernel(const float* __restrict__ x, const int* __restrict__ pids,
                 const float* __restrict__ W1, const float* __restrict__ b1,
                 const float* __restrict__ W2, const float* __restrict__ b2,
                 float* __restrict__ out, int has_pids) {
    extern __shared__ float dynsm[];
    float* sXT   = dynsm;                                  // [KC][XSTRIDE] transposed x chunk
    ull*   sWd   = (ull*)(dynsm + KC * XSTRIDE);           // [128][32] dup pairs {w,w}
    float* sScore = (float*)(sWd + D * DH);                // [TILE_M]
    __shared__ float sW2[DH];
    __shared__ float sB1[DH];
    __shared__ int   sStart[SEG_PER_BLOCK + 1];
    __shared__ float sDen[SEG_PER_BLOCK];

    const int tid  = threadIdx.x;
    const int tx   = tid & 31;     // lane
    const int ty   = tid >> 5;     // warp id
    const int hg   = ty & 3;       // hidden group: hidden [hg*8, hg*8+8)
    const int rg   = ty >> 2;      // row group: row-pairs [rg*64, rg*64+64)
    const int seg0 = blockIdx.x * SEG_PER_BLOCK;

    if (tid <= SEG_PER_BLOCK) sStart[tid] = g_seg_start[seg0 + tid];
    if (tid < DH) { sW2[tid] = W2[tid]; sB1[tid] = b1[tid]; }
    if (tid < SEG_PER_BLOCK) sDen[tid] = 0.f;
    for (int i = tid; i < D * DH; i += THREADS) {
        float w = W1[i];
        sWd[i] = pack2(w, w);
    }
    sScore[tid] = 0.f;
    const float b2v = b2[0];
    __syncthreads();

    const int rbeg = sStart[0], rend = sStart[SEG_PER_BLOCK];
    const int nTiles = (rend - rbeg + TILE_M - 1) / TILE_M;

    float4 buf[8];
    if (nTiles > 0) ldg_chunk(x, rbeg, 0, rend, tid, buf);

    const int xoff = rg * 64 + tx;   // first row-pair this thread owns

    // ---- Phase A: register-blocked score GEMM + exp + shared denom ----
    for (int t = 0; t < nTiles; ++t) {
        const int tbase = rbeg + t * TILE_M;
        ull acc[2][8];
        #pragma unroll
        for (int j = 0; j < 2; ++j)
            #pragma unroll
            for (int jh = 0; jh < 8; ++jh) acc[j][jh] = 0ULL;

        for (int c = 0; c < NCHUNK; ++c) {
            __syncthreads();   // previous compute done reading sXT
            // stage chunk c from prefetch regs (transposed)
            #pragma unroll
            for (int i = 0; i < 8; ++i) {
                int idx = tid + THREADS * i;
                int row = idx >> 3;
                int kq  = idx & 7;
                float* dst = sXT + (kq * 4) * XSTRIDE + row;
                dst[0 * XSTRIDE] = buf[i].x;
                dst[1 * XSTRIDE] = buf[i].y;
                dst[2 * XSTRIDE] = buf[i].z;
                dst[3 * XSTRIDE] = buf[i].w;
            }
            __syncthreads();
            // prefetch next chunk (next k-chunk, or next tile's chunk 0)
            int nc = c + 1, nb = tbase;
            if (nc == NCHUNK) { nc = 0; nb += TILE_M; }
            if (nb < rend) ldg_chunk(x, nb, nc * KC, rend, tid, buf);

            // compute: 32 k-steps x 16 fma2 per thread
            const int k0 = c * KC;
            #pragma unroll 8
            for (int kk = 0; kk < KC; ++kk) {
                const ull* xrow = (const ull*)(sXT + kk * XSTRIDE);
                ull xp0 = xrow[xoff];
                ull xp1 = xrow[xoff + 32];
                const ulonglong2* wr =
                    (const ulonglong2*)(sWd + (k0 + kk) * DH + hg * 8);
                ulonglong2 wa = wr[0], wb = wr[1], wc = wr[2], wd = wr[3];
                acc[0][0] = fma2(xp0, wa.x, acc[0][0]);
                acc[0][1] = fma2(xp0, wa.y, acc[0][1]);
                acc[0][2] = fma2(xp0, wb.x, acc[0][2]);
                acc[0][3] = fma2(xp0, wb.y, acc[0][3]);
                acc[0][4] = fma2(xp0, wc.x, acc[0][4]);
                acc[0][5] = fma2(xp0, wc.y, acc[0][5]);
                acc[0][6] = fma2(xp0, wd.x, acc[0][6]);
                acc[0][7] = fma2(xp0, wd.y, acc[0][7]);
                acc[1][0] = fma2(xp1, wa.x, acc[1][0]);
                acc[1][1] = fma2(xp1, wa.y, acc[1][1]);
                acc[1][2] = fma2(xp1, wb.x, acc[1][2]);
                acc[1][3] = fma2(xp1, wb.y, acc[1][3]);
                acc[1][4] = fma2(xp1, wc.x, acc[1][4]);
                acc[1][5] = fma2(xp1, wc.y, acc[1][5]);
                acc[1][6] = fma2(xp1, wd.x, acc[1][6]);
                acc[1][7] = fma2(xp1, wd.y, acc[1][7]);
            }
        }

        // partial scores: tanh + W2 over this thread's 8 hidden, per row-pair
        #pragma unroll
        for (int j = 0; j < 2; ++j) {
            float slo = 0.f, shi = 0.f;
            #pragma unroll
            for (int jh = 0; jh < 8; ++jh) {
                int h = hg * 8 + jh;
                float lo, hi;
                unpack2(acc[j][jh], lo, hi);
                slo += tanh_fast(lo + sB1[h]) * sW2[h];
                shi += tanh_fast(hi + sB1[h]) * sW2[h];
            }
            int p = xoff + 32 * j;           // row-pair index 0..127
            atomicAdd(&sScore[2 * p],     slo);
            atomicAdd(&sScore[2 * p + 1], shi);
        }
        __syncthreads();

        // finalize: one thread per row. |score| <= ~6 analytically, exp safe.
        int row = tbase + tid;
        if (row < rend) {
            float e = __expf(sScore[tid] + b2v);
            g_e[row] = e;
            atomicAdd(&sDen[pids[row] - seg0], e);
        }
        sScore[tid] = 0.f;   // own slot only; next tile's atomics are sync-ordered after this
    }
    __syncthreads();

    // ---- Phase B: weighted pooling; warp ty handles segments ty, ty+8 ----
    for (int s = ty; s < SEG_PER_BLOCK; s += 8) {
        const int a = sStart[s], bnd = sStart[s + 1];
        const float den  = sDen[s];
        const float dinv = den > 0.f ? 1.f / den : 0.f;
        float4 acc4 = make_float4(0.f, 0.f, 0.f, 0.f);
        #pragma unroll 8
        for (int r = a; r < bnd; ++r) {
            float w = g_e[r] * dinv;
            float4 xv = *(const float4*)(x + r * D + tx * 4);
            acc4.x = fmaf(w, xv.x, acc4.x);
            acc4.y = fmaf(w, xv.y, acc4.y);
            acc4.z = fmaf(w, xv.z, acc4.z);
            acc4.w = fmaf(w, xv.w, acc4.w);
        }
        *(float4*)(out + (seg0 + s) * D + tx * 4) = acc4;
    }

    // ---- pooled_pids tail (arange), if the output buffer includes it ----
    if (has_pids && tid < SEG_PER_BLOCK) {
        out[P_SEG * D + seg0 + tid] = (float)(seg0 + tid);
    }
}

extern "C" void kernel_launch(void* const* d_in, const int* in_sizes, int n_in,
                              void* d_out, int out_size) {
    const float* x   = (const float*)d_in[0];
    const int*   pid = (const int*)d_in[1];
    const float* W1  = (const float*)d_in[2];
    const float* b1  = (const float*)d_in[3];
    const float* W2  = (const float*)d_in[4];
    const float* b2  = (const float*)d_in[5];
    const int n = in_sizes[1];
    const int has_pids = (out_size >= P_SEG * D + P_SEG) ? 1 : 0;

    seg_bounds_kernel<<<(P_SEG + 1 + 255) / 256, 256>>>(pid, n);

    const int smem_bytes = (KC * XSTRIDE) * 4 + (D * DH) * 8 + TILE_M * 4;
    cudaFuncSetAttribute((const void*)pool_kernel,
                         cudaFuncAttributeMaxDynamicSharedMemorySize,
                         smem_bytes);
    pool_kernel<<<NBLOCKS, THREADS, smem_bytes>>>(
        x, pid, W1, b1, W2, b2, (float*)d_out, has_pids);
}

// round 8
// speedup vs baseline: 2.6853x; 1.0406x over previous
#include <cuda_runtime.h>
#include <cstdint>

#define D        128
#define DH       32
#define NKP      (D / 2)            // 64 k-pairs
#define P_SEG    16384
#define SEG_PER_BLOCK 16
#define NBLOCKS  (P_SEG / SEG_PER_BLOCK)
#define THREADS  256
#define TILE_M   128
#define KC       32                 // floats per staged chunk (16 k-pairs)
#define KPC      (KC / 2)
#define NCHUNK   (D / KC)           // 4
#define XROW_ULL 17                 // 8B units per staged row (odd -> conflict-free)
#define NROWS_MAX 1000000

__device__ int   g_seg_start[P_SEG + 1];
__device__ float g_e[NROWS_MAX];

typedef unsigned long long ull;

__device__ __forceinline__ ull pack2(float lo, float hi) {
    ull r;
    asm("mov.b64 %0, {%1, %2};" : "=l"(r) : "f"(lo), "f"(hi));
    return r;
}
__device__ __forceinline__ void unpack2(ull v, float& lo, float& hi) {
    asm("mov.b64 {%0, %1}, %2;" : "=f"(lo), "=f"(hi) : "l"(v));
}
// Packed dual-fp32 FMA (FFMA2) — 2x fp32 MAC throughput on sm_103a
__device__ __forceinline__ ull fma2(ull a, ull b, ull c) {
    ull d;
    asm("fma.rn.f32x2 %0, %1, %2, %3;" : "=l"(d) : "l"(a), "l"(b), "l"(c));
    return d;
}
// Single-instruction tanh (MUFU-class). Abs err ~1e-5 -> pooled err << 1e-3.
__device__ __forceinline__ float tanh_fast(float x) {
    float y;
    asm("tanh.approx.f32 %0, %1;" : "=f"(y) : "f"(x));
    return y;
}

// Kernel 1: segment boundaries via binary search over sorted person_ids.
__global__ void seg_bounds_kernel(const int* __restrict__ pids, int n) {
    int p = blockIdx.x * blockDim.x + threadIdx.x;
    if (p > P_SEG) return;
    int lo = 0, hi = n;
    while (lo < hi) {
        int mid = (lo + hi) >> 1;
        if (pids[mid] < p) lo = mid + 1; else hi = mid;
    }
    g_seg_start[p] = lo;
}

// Prefetch one 128-row x 32-float chunk into registers (4 float4 / thread).
__device__ __forceinline__ void ldg_chunk(const float* __restrict__ x,
                                          int tbase, int k0, int rend, int tid,
                                          float4* buf) {
    #pragma unroll
    for (int i = 0; i < 4; ++i) {
        int idx = tid + THREADS * i;
        int row = idx >> 3;          // 0..127
        int kq  = idx & 7;           // float4 within the 32-float chunk
        int r   = tbase + row;
        if (r < rend)
            buf[i] = *(const float4*)(x + r * D + k0 + kq * 4);
        else
            buf[i] = make_float4(0.f, 0.f, 0.f, 0.f);
    }
}

// Kernel 2: fused scores + segment softmax + weighted pooling.
// One block owns 16 contiguous segments (a contiguous row range).
// k-pair packing: f32x2 lanes hold adjacent k; lo+hi at epilogue sums them.
// Thread tile: 2 rows x 8 hidden. 8 warps = 2 row-groups x 4 hidden-groups.
__global__ __launch_bounds__(THREADS, 3)
void pool_kernel(const float* __restrict__ x, const int* __restrict__ pids,
                 const float* __restrict__ W1, const float* __restrict__ b1,
                 const float* __restrict__ W2, const float* __restrict__ b2,
                 float* __restrict__ out, int has_pids) {
    extern __shared__ float dynsm[];
    ull*   sX   = (ull*)dynsm;                       // [TILE_M][17] k-pair rows
    ull*   sWp  = sX + TILE_M * XROW_ULL;            // [64][32] {W[2k][h],W[2k+1][h]}
    float* sSc  = (float*)(sWp + NKP * DH);          // [4][TILE_M] per-hg partials
    __shared__ float sW2[DH];
    __shared__ float sB1[DH];
    __shared__ int   sStart[SEG_PER_BLOCK + 1];
    __shared__ float sDen[SEG_PER_BLOCK];

    const int tid  = threadIdx.x;
    const int tx   = tid & 31;     // lane
    const int ty   = tid >> 5;     // warp id
    const int hg   = ty & 3;       // hidden group: hidden [hg*8, hg*8+8)
    const int rg   = ty >> 2;      // row group: rows [rg*64, rg*64+64)
    const int seg0 = blockIdx.x * SEG_PER_BLOCK;

    if (tid <= SEG_PER_BLOCK) sStart[tid] = g_seg_start[seg0 + tid];
    if (tid < DH) { sW2[tid] = W2[tid]; sB1[tid] = b1[tid]; }
    if (tid < SEG_PER_BLOCK) sDen[tid] = 0.f;
    for (int i = tid; i < NKP * DH; i += THREADS) {
        int kp = i >> 5, h = i & 31;
        sWp[i] = pack2(W1[(2 * kp) * DH + h], W1[(2 * kp + 1) * DH + h]);
    }
    const float b2v = b2[0];
    __syncthreads();

    const int rbeg = sStart[0], rend = sStart[SEG_PER_BLOCK];
    const int nTiles = (rend - rbeg + TILE_M - 1) / TILE_M;

    float4 buf[4];
    if (nTiles > 0) ldg_chunk(x, rbeg, 0, rend, tid, buf);

    const int row0 = rg * 64 + tx;   // this thread's rows: row0, row0+32

    // ---- Phase A: register-blocked score GEMM + exp + shared denom ----
    for (int t = 0; t < nTiles; ++t) {
        const int tbase = rbeg + t * TILE_M;
        ull acc[2][8];
        #pragma unroll
        for (int j = 0; j < 2; ++j)
            #pragma unroll
            for (int jh = 0; jh < 8; ++jh) acc[j][jh] = 0ULL;

        for (int c = 0; c < NCHUNK; ++c) {
            __syncthreads();   // previous compute done reading sX
            // stage chunk c (straight copy, no transpose): float2 = 8B stores
            #pragma unroll
            for (int i = 0; i < 4; ++i) {
                int idx = tid + THREADS * i;
                int row = idx >> 3;
                int kq  = idx & 7;
                float2* dst = (float2*)(sX + row * XROW_ULL + kq * 2);
                dst[0] = make_float2(buf[i].x, buf[i].y);
                dst[1] = make_float2(buf[i].z, buf[i].w);
            }
            __syncthreads();
            // prefetch next chunk (next k-chunk, or next tile's chunk 0)
            int nc = c + 1, nb = tbase;
            if (nc == NCHUNK) { nc = 0; nb += TILE_M; }
            if (nb < rend) ldg_chunk(x, nb, nc * KC, rend, tid, buf);

            // compute: 16 k-pair steps x 16 fma2 per thread
            const int kp0 = c * KPC;
            #pragma unroll 8
            for (int kk = 0; kk < KPC; ++kk) {
                ull xp0 = sX[row0 * XROW_ULL + kk];
                ull xp1 = sX[(row0 + 32) * XROW_ULL + kk];
                const ulonglong2* wr =
                    (const ulonglong2*)(sWp + (kp0 + kk) * DH + hg * 8);
                ulonglong2 wa = wr[0], wb = wr[1], wc = wr[2], wd = wr[3];
                acc[0][0] = fma2(xp0, wa.x, acc[0][0]);
                acc[0][1] = fma2(xp0, wa.y, acc[0][1]);
                acc[0][2] = fma2(xp0, wb.x, acc[0][2]);
                acc[0][3] = fma2(xp0, wb.y, acc[0][3]);
                acc[0][4] = fma2(xp0, wc.x, acc[0][4]);
                acc[0][5] = fma2(xp0, wc.y, acc[0][5]);
                acc[0][6] = fma2(xp0, wd.x, acc[0][6]);
                acc[0][7] = fma2(xp0, wd.y, acc[0][7]);
                acc[1][0] = fma2(xp1, wa.x, acc[1][0]);
                acc[1][1] = fma2(xp1, wa.y, acc[1][1]);
                acc[1][2] = fma2(xp1, wb.x, acc[1][2]);
                acc[1][3] = fma2(xp1, wb.y, acc[1][3]);
                acc[1][4] = fma2(xp1, wc.x, acc[1][4]);
                acc[1][5] = fma2(xp1, wc.y, acc[1][5]);
                acc[1][6] = fma2(xp1, wd.x, acc[1][6]);
                acc[1][7] = fma2(xp1, wd.y, acc[1][7]);
            }
        }

        // partial scores: tanh + W2 over this thread's 8 hidden, per row.
        // lo+hi collapses the even/odd-k subsums; +b1 once per hidden here.
        #pragma unroll
        for (int j = 0; j < 2; ++j) {
            float s = 0.f;
            #pragma unroll
            for (int jh = 0; jh < 8; ++jh) {
                int h = hg * 8 + jh;
                float lo, hi;
                unpack2(acc[j][jh], lo, hi);
                s += tanh_fast(lo + hi + sB1[h]) * sW2[h];
            }
            sSc[hg * TILE_M + row0 + 32 * j] = s;   // plain store, no atomics
        }
        __syncthreads();

        // finalize: one thread per row. |score| <= ~6 analytically, exp safe.
        if (tid < TILE_M) {
            int row = tbase + tid;
            if (row < rend) {
                float sc = sSc[tid] + sSc[TILE_M + tid] +
                           sSc[2 * TILE_M + tid] + sSc[3 * TILE_M + tid] + b2v;
                float e = __expf(sc);
                g_e[row] = e;
                atomicAdd(&sDen[pids[row] - seg0], e);
            }
        }
    }
    __syncthreads();

    // ---- Phase B: weighted pooling; warp ty handles segments ty, ty+8 ----
    for (int s = ty; s < SEG_PER_BLOCK; s += 8) {
        const int a = sStart[s], bnd = sStart[s + 1];
        const float den  = sDen[s];
        const float dinv = den > 0.f ? 1.f / den : 0.f;
        float4 acc4 = make_float4(0.f, 0.f, 0.f, 0.f);
        #pragma unroll 8
        for (int r = a; r < bnd; ++r) {
            float w = g_e[r] * dinv;
            float4 xv = *(const float4*)(x + r * D + tx * 4);
            acc4.x = fmaf(w, xv.x, acc4.x);
            acc4.y = fmaf(w, xv.y, acc4.y);
            acc4.z = fmaf(w, xv.z, acc4.z);
            acc4.w = fmaf(w, xv.w, acc4.w);
        }
        *(float4*)(out + (seg0 + s) * D + tx * 4) = acc4;
    }

    // ---- pooled_pids tail (arange), if the output buffer includes it ----
    if (has_pids && tid < SEG_PER_BLOCK) {
        out[P_SEG * D + seg0 + tid] = (float)(seg0 + tid);
    }
}

extern "C" void kernel_launch(void* const* d_in, const int* in_sizes, int n_in,
                              void* d_out, int out_size) {
    const float* x   = (const float*)d_in[0];
    const int*   pid = (const int*)d_in[1];
    const float* W1  = (const float*)d_in[2];
    const float* b1  = (const float*)d_in[3];
    const float* W2  = (const float*)d_in[4];
    const float* b2  = (const float*)d_in[5];
    const int n = in_sizes[1];
    const int has_pids = (out_size >= P_SEG * D + P_SEG) ? 1 : 0;

    seg_bounds_kernel<<<(P_SEG + 1 + 255) / 256, 256>>>(pid, n);

    const int smem_bytes = TILE_M * XROW_ULL * 8      // sX
                         + NKP * DH * 8               // sWp
                         + 4 * TILE_M * 4;            // sSc
    cudaFuncSetAttribute((const void*)pool_kernel,
                         cudaFuncAttributeMaxDynamicSharedMemorySize,
                         smem_bytes);
    pool_kernel<<<NBLOCKS, THREADS, smem_bytes>>>(
        x, pid, W1, b1, W2, b2, (float*)d_out, has_pids);
}